// round 16
// baseline (speedup 1.0000x reference)
#include <cuda_runtime.h>
#include <cuda_fp16.h>
#include <stdint.h>
#include <math.h>

#define B 8
#define SL 4096
#define D 128
#define NH 8
#define NB 64
#define NC 512
#define BS 64
#define NSL (NH*SL)
#define MNEG (-3.402823466e38f)

typedef unsigned long long ull;

__device__ __forceinline__ void fma2(ull& d, ull a, ull b) {
    asm("fma.rn.f32x2 %0, %1, %2, %0;" : "+l"(d) : "l"(a), "l"(b));
}
__device__ __forceinline__ ull pack2(float lo, float hi) {
    ull r; asm("mov.b64 %0, {%1, %2};" : "=l"(r) : "f"(lo), "f"(hi)); return r;
}
__device__ __forceinline__ float2 unpack2(ull v) {
    float2 r; asm("mov.b64 {%0, %1}, %2;" : "=f"(r.x), "=f"(r.y) : "l"(v)); return r;
}
__device__ __forceinline__ uint32_t smem_u32(const void* p) {
    uint32_t a;
    asm("{ .reg .u64 t; cvta.to.shared.u64 t, %1; cvt.u32.u64 %0, t; }" : "=r"(a) : "l"(p));
    return a;
}

// ---- warp-level tensor core primitives (portable PTX, HMMA pipe) ----
#define LDSM_X4(r0, r1, r2, r3, a) \
    asm volatile("ldmatrix.sync.aligned.m8n8.x4.shared.b16 {%0,%1,%2,%3}, [%4];" \
        : "=r"(r0), "=r"(r1), "=r"(r2), "=r"(r3) : "r"(a))
#define LDSM_X2(r0, r1, a) \
    asm volatile("ldmatrix.sync.aligned.m8n8.x2.shared.b16 {%0,%1}, [%2];" \
        : "=r"(r0), "=r"(r1) : "r"(a))
#define LDSM_X2T(r0, r1, a) \
    asm volatile("ldmatrix.sync.aligned.m8n8.x2.trans.shared.b16 {%0,%1}, [%2];" \
        : "=r"(r0), "=r"(r1) : "r"(a))
#define MMA16816(c, a0, a1, a2, a3, b0, b1) \
    asm volatile("mma.sync.aligned.m16n8k16.row.col.f32.f16.f16.f32 " \
        "{%0,%1,%2,%3}, {%4,%5,%6,%7}, {%8,%9}, {%0,%1,%2,%3};" \
        : "+f"((c)[0]), "+f"((c)[1]), "+f"((c)[2]), "+f"((c)[3]) \
        : "r"(a0), "r"(a1), "r"(a2), "r"(a3), "r"(b0), "r"(b1))

// ---- k_attn smem layout (bytes). fp16 rows, stride 136 halves = 272 B ----
#define RSB 272
#define QHOFF 0         // Q fp16 64 rows; reused as P fp16
#define KHOFF 17408     // K fp16 128 rows; reused as V fp16
#define IOFF  52224     // ints: qt64 qb64 kt128 kb128 ql1[512] kl[2048]
#define RMAXOFF 64000   // float[64*4]
#define RSUMOFF 65024   // float[64*4]
#define SMEM_ATTN 66048

// ---------------- scratch ----------------------------------------------------
__device__ int    g_buckets[B][NH][SL];
__device__ int    g_hist[B][NC];
__device__ int    g_boff[B][NC];
__device__ int    g_sticker[B][NSL];
__device__ int    g_undo[B][NSL];
__device__ int    g_slocT[B][NSL][16];  // sorted loc pairs {loc1[h], loc2[h]}
__device__ __half g_Qh[B][NSL][D];      // sorted raw q, fp16
__device__ __half g_Kh[B][NSL][D];      // sorted normalized k, fp16
__device__ __half g_Vh[B][NSL][D];      // sorted v, fp16
__device__ __half g_so[B][NSL][D];
__device__ float  g_slog[B][NSL];

__global__ void k_zero_hist() { g_hist[blockIdx.x][threadIdx.x] = 0; }

__global__ void k_buckets(const float* __restrict__ qk, const float* __restrict__ rot) {
    __shared__ float rs[32 * 32];
    __shared__ float qt_[256 * 33];
    int b = blockIdx.z, h = blockIdx.y, tid = threadIdx.x;
    int s0 = blockIdx.x * 256;
    ull acc2[16];
#pragma unroll
    for (int n = 0; n < 16; n++) acc2[n] = 0ull;
    for (int d0 = 0; d0 < 128; d0 += 32) {
        for (int i = tid; i < 32 * 32; i += 256) {
            int dd = i >> 5, nn = i & 31;
            rs[i] = rot[((size_t)(d0 + dd) * NH + h) * 32 + nn];
        }
        for (int i = tid; i < 256 * 32; i += 256) {
            int r = i >> 5, c = i & 31;
            qt_[r * 33 + c] = qk[((size_t)b * SL + s0 + r) * D + d0 + c];
        }
        __syncthreads();
#pragma unroll 4
        for (int dd = 0; dd < 32; dd++) {
            float qv = qt_[tid * 33 + dd];
            ull qq = pack2(qv, qv);
            const ull* r2 = (const ull*)&rs[dd * 32];
#pragma unroll
            for (int n = 0; n < 16; n++) fma2(acc2[n], qq, r2[n]);
        }
        __syncthreads();
    }
    float acc[32];
#pragma unroll
    for (int n = 0; n < 16; n++) { float2 p = unpack2(acc2[n]); acc[2*n] = p.x; acc[2*n+1] = p.y; }
    float best = acc[0]; int idx = 0;
#pragma unroll
    for (int n = 1; n < 32; n++) if (acc[n] > best) { best = acc[n]; idx = n; }
#pragma unroll
    for (int n = 0; n < 32; n++) if (-acc[n] > best) { best = -acc[n]; idx = 32 + n; }
    int bucket = idx + h * NB;
    g_buckets[b][h][s0 + tid] = bucket;
    atomicAdd(&g_hist[b][bucket], 1);
}

__global__ void k_prefix() {
    __shared__ int sh[NC];
    int b = blockIdx.x, tid = threadIdx.x;
    int v = g_hist[b][tid];
    sh[tid] = v;
    __syncthreads();
#pragma unroll
    for (int off = 1; off < NC; off <<= 1) {
        int x = (tid >= off) ? sh[tid - off] : 0;
        __syncthreads();
        sh[tid] += x;
        __syncthreads();
    }
    g_boff[b][tid] = sh[tid] - v;
}

__global__ void k_scatter() {
    int bk = blockIdx.x, b = blockIdx.y;
    int h = bk >> 6;
    int warp = threadIdx.x >> 5, lane = threadIdx.x & 31;
    const int* bb = &g_buckets[b][h][0];
    int t0 = warp * (SL / 4);
    __shared__ int wc[4];
    int cnt = 0;
    for (int base = 0; base < SL / 4; base += 32) {
        bool m = (bb[t0 + base + lane] == bk);
        cnt += __popc(__ballot_sync(0xffffffffu, m));
    }
    if (lane == 0) wc[warp] = cnt;
    __syncthreads();
    int pos = g_boff[b][bk];
#pragma unroll
    for (int w = 0; w < 4; w++) if (w < warp) pos += wc[w];
    for (int base = 0; base < SL / 4; base += 32) {
        int t = t0 + base + lane;
        bool m = (bb[t] == bk);
        unsigned bal = __ballot_sync(0xffffffffu, m);
        if (m) {
            int r = __popc(bal & ((1u << lane) - 1));
            int j = h * SL + t;
            g_sticker[b][pos + r] = j;
            g_undo[b][j] = pos + r;
        }
        pos += __popc(bal);
    }
}

// loc codes scatter-written directly into sorted order.
__global__ void k_loc() {
    int idx = blockIdx.x * 128 + threadIdx.x;
    int b = idx >> 12, t = idx & (SL - 1);
    int pos[NH], val[16];
#pragma unroll
    for (int h = 0; h < NH; h++) {
        int bucket = g_buckets[b][h][t];
        pos[h] = g_undo[b][h * SL + t];
        int chunk = pos[h] >> 6;
        val[2 * h]     = bucket * NC + chunk;
        val[2 * h + 1] = bucket * NC + ((chunk + 1) & (NC - 1));
    }
    int4 v0 = make_int4(val[0], val[1], val[2], val[3]);
    int4 v1 = make_int4(val[4], val[5], val[6], val[7]);
    int4 v2 = make_int4(val[8], val[9], val[10], val[11]);
    int4 v3 = make_int4(val[12], val[13], val[14], val[15]);
#pragma unroll
    for (int h = 0; h < NH; h++) {
        int4* dst = (int4*)&g_slocT[b][pos[h]][0];
        dst[0] = v0; dst[1] = v1; dst[2] = v2; dst[3] = v3;
    }
}

// streaming convert: gather token rows once into sorted fp16 arrays.
// grid (NSL/64, B), block 256 (8 warps); warp handles 8 sorted rows.
__global__ void __launch_bounds__(256)
k_convert(const float* __restrict__ qk, const float* __restrict__ v) {
    int b = blockIdx.y;
    int p0 = blockIdx.x * 64;
    int warp = threadIdx.x >> 5, lane = threadIdx.x & 31;
    int tf[8];
#pragma unroll
    for (int u = 0; u < 8; u++) tf[u] = g_sticker[b][p0 + warp + 8 * u];
#pragma unroll
    for (int u = 0; u < 8; u++) {
        int p = p0 + warp + 8 * u;
        int t = tf[u] & (SL - 1);
        float4 x  = ((const float4*)(qk + ((size_t)b * SL + t) * D))[lane];
        float4 vx = ((const float4*)(v  + ((size_t)b * SL + t) * D))[lane];
        __half2 q0 = __floats2half2_rn(x.x, x.y);
        __half2 q1 = __floats2half2_rn(x.z, x.w);
        ((uint2*)&g_Qh[b][p][0])[lane] = make_uint2(*(uint32_t*)&q0, *(uint32_t*)&q1);
        float ss = x.x * x.x + x.y * x.y + x.z * x.z + x.w * x.w;
#pragma unroll
        for (int o = 16; o > 0; o >>= 1) ss += __shfl_xor_sync(0xffffffffu, ss, o);
        float inv = rsqrtf(fmaxf(ss, 1e-24f));
        __half2 k0 = __floats2half2_rn(x.x * inv, x.y * inv);
        __half2 k1 = __floats2half2_rn(x.z * inv, x.w * inv);
        ((uint2*)&g_Kh[b][p][0])[lane] = make_uint2(*(uint32_t*)&k0, *(uint32_t*)&k1);
        __half2 w0 = __floats2half2_rn(vx.x, vx.y);
        __half2 w1 = __floats2half2_rn(vx.z, vx.w);
        ((uint2*)&g_Vh[b][p][0])[lane] = make_uint2(*(uint32_t*)&w0, *(uint32_t*)&w1);
    }
}

// Tensor-core attention, fully coalesced loads. grid (NC, B), block 512, 3 blocks/SM.
__global__ void __launch_bounds__(512, 3)
k_attn() {
    extern __shared__ char smemc[];
    int n = blockIdx.x, b = blockIdx.y;
    int tid = threadIdx.x, warp = tid >> 5, lane = tid & 31;
    int sg = warp >> 2, zg = warp & 3;
    int gid = lane >> 2, tig = lane & 3;

    int* qt  = (int*)(smemc + IOFF);
    int* qb  = qt + 64;
    int* kt  = qt + 128;
    int* kb  = qt + 256;
    int* ql1 = qt + 384;
    int* kl  = qt + 896;
    float* rmax = (float*)(smemc + RMAXOFF);
    float* rsum = (float*)(smemc + RSUMOFF);

    int prev = (n + NC - 1) & (NC - 1);

    // ---- coalesced loads of sorted rows ----
#pragma unroll
    for (int u = 0; u < 4; u++) {
        int s = warp + 16 * u;
        int p = n * BS + s;
        int tf = g_sticker[b][p];
        int t = tf & (SL - 1), h = tf >> 12;
        ((uint2*)(smemc + QHOFF + s * RSB))[lane] = ((const uint2*)&g_Qh[b][p][0])[lane];
        ((uint2*)(smemc + KHOFF + s * RSB))[lane] = ((const uint2*)&g_Kh[b][p][0])[lane];
        if (lane == 0) { qt[s] = t; kt[s] = t; }
        if (lane < 4) {
            int4 lv = ((const int4*)&g_slocT[b][p][0])[lane];
            *(int4*)&kl[s * 16 + 4 * lane] = lv;
            ql1[s * 8 + 2 * lane]     = lv.x;
            ql1[s * 8 + 2 * lane + 1] = lv.z;
            if (lane == (h >> 1)) {
                int bkt = ((h & 1) ? lv.z : lv.x) >> 9;
                kb[s] = bkt; qb[s] = bkt;
            }
        }
    }
#pragma unroll
    for (int u = 0; u < 4; u++) {
        int s = warp + 16 * u;
        int z = 64 + s;
        int p = prev * BS + s;
        int tf = g_sticker[b][p];
        int t = tf & (SL - 1), h = tf >> 12;
        ((uint2*)(smemc + KHOFF + z * RSB))[lane] = ((const uint2*)&g_Kh[b][p][0])[lane];
        if (lane == 0) kt[z] = t;
        if (lane < 4) {
            int4 lv = ((const int4*)&g_slocT[b][p][0])[lane];
            *(int4*)&kl[z * 16 + 4 * lane] = lv;
            if (lane == (h >> 1)) kb[z] = ((h & 1) ? lv.z : lv.x) >> 9;
        }
    }
    __syncthreads();

    // ---- QK via mma.sync: warp computes S[16 s, 32 z] over k=128 ----
    float acc[4][4];
#pragma unroll
    for (int nt = 0; nt < 4; nt++)
#pragma unroll
        for (int j = 0; j < 4; j++) acc[nt][j] = 0.f;

    uint32_t aQ = smem_u32(smemc) + QHOFF + (16 * sg + (lane & 15)) * RSB + ((lane >> 4) * 8) * 2;
    uint32_t aK = smem_u32(smemc) + KHOFF + (32 * zg + (lane & 7)) * RSB + (((lane >> 3) & 1) * 8) * 2;
#pragma unroll
    for (int k = 0; k < 8; k++) {
        uint32_t a0, a1, a2, a3;
        LDSM_X4(a0, a1, a2, a3, aQ + k * 32);
#pragma unroll
        for (int nt = 0; nt < 4; nt++) {
            uint32_t b0, b1;
            LDSM_X2(b0, b1, aK + nt * 8 * RSB + k * 32);
            MMA16816(acc[nt], a0, a1, a2, a3, b0, b1);
        }
    }

    // ---- masks + dup correction ----
    int s_a = 16 * sg + gid, s_b = s_a + 8;
    int qt_a = qt[s_a], qb_a = qb[s_a], qt_b = qt[s_b], qb_b = qb[s_b];
    int4 qa1 = *(int4*)&ql1[s_a * 8], qa2 = *(int4*)&ql1[s_a * 8 + 4];
    int4 qb1 = *(int4*)&ql1[s_b * 8], qb2 = *(int4*)&ql1[s_b * 8 + 4];
    const float scale = 0.08838834764831845f;
#pragma unroll
    for (int nt = 0; nt < 4; nt++) {
#pragma unroll
        for (int col = 0; col < 2; col++) {
            int z = 32 * zg + 8 * nt + 2 * tig + col;
            int ktv = kt[z], kbv = kb[z];
            int4 ka = *(int4*)&kl[z * 16 + 0];
            int4 kb4 = *(int4*)&kl[z * 16 + 4];
            int4 kc = *(int4*)&kl[z * 16 + 8];
            int4 kd = *(int4*)&kl[z * 16 + 12];
            float va = acc[nt][col] * scale;
            float vb = acc[nt][col + 2] * scale;
            if (qt_a < ktv)  va = MNEG;
            if (qt_a == ktv) va = -10000.f;
            if (qb_a != kbv) va = MNEG;
            if (qt_b < ktv)  vb = MNEG;
            if (qt_b == ktv) vb = -10000.f;
            if (qb_b != kbv) vb = MNEG;
            int ca = 0, cb = 0;
            ca += (qa1.x == ka.x)  + (qa1.x == ka.y);
            ca += (qa1.y == ka.z)  + (qa1.y == ka.w);
            ca += (qa1.z == kb4.x) + (qa1.z == kb4.y);
            ca += (qa1.w == kb4.z) + (qa1.w == kb4.w);
            ca += (qa2.x == kc.x)  + (qa2.x == kc.y);
            ca += (qa2.y == kc.z)  + (qa2.y == kc.w);
            ca += (qa2.z == kd.x)  + (qa2.z == kd.y);
            ca += (qa2.w == kd.z)  + (qa2.w == kd.w);
            cb += (qb1.x == ka.x)  + (qb1.x == ka.y);
            cb += (qb1.y == ka.z)  + (qb1.y == ka.w);
            cb += (qb1.z == kb4.x) + (qb1.z == kb4.y);
            cb += (qb1.w == kb4.z) + (qb1.w == kb4.w);
            cb += (qb2.x == kc.x)  + (qb2.x == kc.y);
            cb += (qb2.y == kc.z)  + (qb2.y == kc.w);
            cb += (qb2.z == kd.x)  + (qb2.z == kd.y);
            cb += (qb2.w == kd.z)  + (qb2.w == kd.w);
            acc[nt][col]     = va - __logf((float)ca + 1e-9f);
            acc[nt][col + 2] = vb - __logf((float)cb + 1e-9f);
        }
    }

    // ---- single-pass local softmax; store partials ----
    float mxa = MNEG, mxb = MNEG;
#pragma unroll
    for (int nt = 0; nt < 4; nt++) {
        mxa = fmaxf(mxa, fmaxf(acc[nt][0], acc[nt][1]));
        mxb = fmaxf(mxb, fmaxf(acc[nt][2], acc[nt][3]));
    }
#pragma unroll
    for (int o = 1; o <= 2; o <<= 1) {
        mxa = fmaxf(mxa, __shfl_xor_sync(0xffffffffu, mxa, o));
        mxb = fmaxf(mxb, __shfl_xor_sync(0xffffffffu, mxb, o));
    }
    float sa = 0.f, sb = 0.f;
#pragma unroll
    for (int nt = 0; nt < 4; nt++) {
        acc[nt][0] = __expf(acc[nt][0] - mxa);
        acc[nt][1] = __expf(acc[nt][1] - mxa);
        acc[nt][2] = __expf(acc[nt][2] - mxb);
        acc[nt][3] = __expf(acc[nt][3] - mxb);
        sa += acc[nt][0] + acc[nt][1];
        sb += acc[nt][2] + acc[nt][3];
    }
#pragma unroll
    for (int o = 1; o <= 2; o <<= 1) {
        sa += __shfl_xor_sync(0xffffffffu, sa, o);
        sb += __shfl_xor_sync(0xffffffffu, sb, o);
    }
    if (tig == 0) {
        rmax[s_a * 4 + zg] = mxa; rmax[s_b * 4 + zg] = mxb;
        rsum[s_a * 4 + zg] = sa;  rsum[s_b * 4 + zg] = sb;
    }
    __syncthreads();   // QK reads done; K buffer free, partials visible

    // ---- combine softmax; write P over Q buffer ----
    float4 ra = *(float4*)&rmax[s_a * 4];
    float4 rb = *(float4*)&rmax[s_b * 4];
    float ma = fmaxf(fmaxf(ra.x, ra.y), fmaxf(ra.z, ra.w));
    float mb = fmaxf(fmaxf(rb.x, rb.y), fmaxf(rb.z, rb.w));
    float4 sra = *(float4*)&rsum[s_a * 4];
    float4 srb = *(float4*)&rsum[s_b * 4];
    float suma = sra.x * __expf(ra.x - ma) + sra.y * __expf(ra.y - ma)
               + sra.z * __expf(ra.z - ma) + sra.w * __expf(ra.w - ma);
    float sumb = srb.x * __expf(rb.x - mb) + srb.y * __expf(rb.y - mb)
               + srb.z * __expf(rb.z - mb) + srb.w * __expf(rb.w - mb);
    float fa = __expf(mxa - ma) / suma;
    float fb = __expf(mxb - mb) / sumb;
#pragma unroll
    for (int nt = 0; nt < 4; nt++) {
        int z0 = 32 * zg + 8 * nt + 2 * tig;
        __half2 pa = __floats2half2_rn(acc[nt][0] * fa, acc[nt][1] * fa);
        __half2 pb = __floats2half2_rn(acc[nt][2] * fb, acc[nt][3] * fb);
        *(__half2*)(smemc + QHOFF + s_a * RSB + z0 * 2) = pa;
        *(__half2*)(smemc + QHOFF + s_b * RSB + z0 * 2) = pb;
    }
    if (zg == 0 && tig == 0) {
        g_slog[b][n * BS + s_a] = ma + __logf(suma);
        g_slog[b][n * BS + s_b] = mb + __logf(sumb);
    }

    // ---- V load into the freed K buffer (coalesced) ----
#pragma unroll
    for (int u = 0; u < 8; u++) {
        int z = warp + 16 * u;
        int p = (z < 64) ? (n * BS + z) : (prev * BS + (z - 64));
        ((uint2*)(smemc + KHOFF + z * RSB))[lane] = ((const uint2*)&g_Vh[b][p][0])[lane];
    }
    __syncthreads();   // P and V visible

    // ---- PV via mma.sync: O[16 s, 32 d] = P · V ----
    float o[4][4];
#pragma unroll
    for (int nt = 0; nt < 4; nt++)
#pragma unroll
        for (int j = 0; j < 4; j++) o[nt][j] = 0.f;

    uint32_t aP = smem_u32(smemc) + QHOFF + (16 * sg + (lane & 15)) * RSB + ((lane >> 4) * 8) * 2;
    uint32_t aV = smem_u32(smemc) + KHOFF + (lane & 15) * RSB + (32 * zg) * 2;
#pragma unroll
    for (int k = 0; k < 8; k++) {
        uint32_t a0, a1, a2, a3;
        LDSM_X4(a0, a1, a2, a3, aP + k * 32);
#pragma unroll
        for (int nt = 0; nt < 4; nt++) {
            uint32_t b0, b1;
            LDSM_X2T(b0, b1, aV + k * 16 * RSB + nt * 16);
            MMA16816(o[nt], a0, a1, a2, a3, b0, b1);
        }
    }
#pragma unroll
    for (int nt = 0; nt < 4; nt++) {
        int d0 = 32 * zg + 8 * nt + 2 * tig;
        *(__half2*)&g_so[b][n * BS + s_a][d0] = __floats2half2_rn(o[nt][0], o[nt][1]);
        *(__half2*)&g_so[b][n * BS + s_b][d0] = __floats2half2_rn(o[nt][2], o[nt][3]);
    }
}

__global__ void k_combine(float* __restrict__ out) {
    int t = blockIdx.x, b = blockIdx.y;
    int d = threadIdx.x;
    int p[NH];
    float l[NH];
    float m = MNEG;
#pragma unroll
    for (int h = 0; h < NH; h++) {
        p[h] = g_undo[b][h * SL + t];
        l[h] = g_slog[b][p[h]];
        m = fmaxf(m, l[h]);
    }
    float sum = 0.f;
#pragma unroll
    for (int h = 0; h < NH; h++) { l[h] = __expf(l[h] - m); sum += l[h]; }
    float inv = 1.f / sum;
    float acc = 0.f;
#pragma unroll
    for (int h = 0; h < NH; h++) acc += l[h] * inv * __half2float(g_so[b][p[h]][d]);
    out[((size_t)b * SL + t) * D + d] = acc;
}

extern "C" void kernel_launch(void* const* d_in, const int* in_sizes, int n_in,
                              void* d_out, int out_size) {
    (void)in_sizes; (void)n_in; (void)out_size;
    const float* qk  = (const float*)d_in[0];
    const float* v   = (const float*)d_in[1];
    const float* rot = (const float*)d_in[2];
    float* out = (float*)d_out;

    cudaFuncSetAttribute(k_attn, cudaFuncAttributeMaxDynamicSharedMemorySize, SMEM_ATTN);

    k_zero_hist<<<B, NC>>>();
    k_buckets<<<dim3(SL / 256, NH, B), 256>>>(qk, rot);
    k_prefix<<<B, NC>>>();
    k_scatter<<<dim3(NC, B), 128>>>();
    k_loc<<<(B * SL) / 128, 128>>>();
    k_convert<<<dim3(NSL / 64, B), 256>>>(qk, v);
    k_attn<<<dim3(NC, B), 512, SMEM_ATTN>>>();
    k_combine<<<dim3(SL, B), 128>>>(out);
}

// round 17
// speedup vs baseline: 1.1188x; 1.1188x over previous
#include <cuda_runtime.h>
#include <cuda_fp16.h>
#include <stdint.h>
#include <math.h>

#define B 8
#define SL 4096
#define D 128
#define NH 8
#define NB 64
#define NC 512
#define BS 64
#define NSL (NH*SL)
#define MNEG (-3.402823466e38f)

typedef unsigned long long ull;

__device__ __forceinline__ void fma2(ull& d, ull a, ull b) {
    asm("fma.rn.f32x2 %0, %1, %2, %0;" : "+l"(d) : "l"(a), "l"(b));
}
__device__ __forceinline__ ull pack2(float lo, float hi) {
    ull r; asm("mov.b64 %0, {%1, %2};" : "=l"(r) : "f"(lo), "f"(hi)); return r;
}
__device__ __forceinline__ float2 unpack2(ull v) {
    float2 r; asm("mov.b64 {%0, %1}, %2;" : "=f"(r.x), "=f"(r.y) : "l"(v)); return r;
}
__device__ __forceinline__ uint32_t smem_u32(const void* p) {
    uint32_t a;
    asm("{ .reg .u64 t; cvta.to.shared.u64 t, %1; cvt.u32.u64 %0, t; }" : "=r"(a) : "l"(p));
    return a;
}

// ---- warp-level tensor core primitives (portable PTX, HMMA pipe) ----
#define LDSM_X4(r0, r1, r2, r3, a) \
    asm volatile("ldmatrix.sync.aligned.m8n8.x4.shared.b16 {%0,%1,%2,%3}, [%4];" \
        : "=r"(r0), "=r"(r1), "=r"(r2), "=r"(r3) : "r"(a))
#define LDSM_X2(r0, r1, a) \
    asm volatile("ldmatrix.sync.aligned.m8n8.x2.shared.b16 {%0,%1}, [%2];" \
        : "=r"(r0), "=r"(r1) : "r"(a))
#define LDSM_X2T(r0, r1, a) \
    asm volatile("ldmatrix.sync.aligned.m8n8.x2.trans.shared.b16 {%0,%1}, [%2];" \
        : "=r"(r0), "=r"(r1) : "r"(a))
#define MMA16816(c, a0, a1, a2, a3, b0, b1) \
    asm volatile("mma.sync.aligned.m16n8k16.row.col.f32.f16.f16.f32 " \
        "{%0,%1,%2,%3}, {%4,%5,%6,%7}, {%8,%9}, {%0,%1,%2,%3};" \
        : "+f"((c)[0]), "+f"((c)[1]), "+f"((c)[2]), "+f"((c)[3]) \
        : "r"(a0), "r"(a1), "r"(a2), "r"(a3), "r"(b0), "r"(b1))

// ---- k_attn smem layout (bytes). fp16 rows, stride 136 halves = 272 B ----
#define RSB 272
#define QHOFF 0         // Q fp16 64 rows; reused as P fp16
#define KHOFF 17408     // K fp16 128 rows; reused as V fp16
#define IOFF  52224     // ints: qt64 qb64 kt128 kb128 ql1[512] kl[2048]
#define RMAXOFF 64000   // float[64*4]
#define RSUMOFF 65024   // float[64*4]
#define SMEM_ATTN 66048

// ---------------- scratch ----------------------------------------------------
__device__ int    g_buckets[B][NH][SL];
__device__ int    g_hist[B][NC];
__device__ int    g_boff[B][NC];
__device__ int    g_sticker[B][NSL];
__device__ int    g_undo[B][NSL];
__device__ int    g_locT[B][SL][16];   // token-order loc pairs {loc1[h], loc2[h]}
__device__ __half g_Qh[B][SL][D];      // token-order raw q, fp16 (8.4 MB)
__device__ __half g_Kh[B][SL][D];      // token-order normalized k, fp16
__device__ __half g_Vh[B][SL][D];      // token-order v, fp16
__device__ __half g_so[B][NSL][D];
__device__ float  g_slog[B][NSL];

__global__ void k_zero_hist() { g_hist[blockIdx.x][threadIdx.x] = 0; }

// token-order fp16 conversion: Qh (raw), Kh (normalized), Vh.
// grid (SL/64, B), block 256 (8 warps); warp handles 8 token rows.
__global__ void __launch_bounds__(256)
k_tok(const float* __restrict__ qk, const float* __restrict__ v) {
    int b = blockIdx.y;
    int t0 = blockIdx.x * 64;
    int warp = threadIdx.x >> 5, lane = threadIdx.x & 31;
#pragma unroll
    for (int u = 0; u < 8; u++) {
        int t = t0 + warp + 8 * u;
        float4 x  = ((const float4*)(qk + ((size_t)b * SL + t) * D))[lane];
        float4 vx = ((const float4*)(v  + ((size_t)b * SL + t) * D))[lane];
        __half2 q0 = __floats2half2_rn(x.x, x.y);
        __half2 q1 = __floats2half2_rn(x.z, x.w);
        ((uint2*)&g_Qh[b][t][0])[lane] = make_uint2(*(uint32_t*)&q0, *(uint32_t*)&q1);
        float ss = x.x * x.x + x.y * x.y + x.z * x.z + x.w * x.w;
#pragma unroll
        for (int o = 16; o > 0; o >>= 1) ss += __shfl_xor_sync(0xffffffffu, ss, o);
        float inv = rsqrtf(fmaxf(ss, 1e-24f));
        __half2 k0 = __floats2half2_rn(x.x * inv, x.y * inv);
        __half2 k1 = __floats2half2_rn(x.z * inv, x.w * inv);
        ((uint2*)&g_Kh[b][t][0])[lane] = make_uint2(*(uint32_t*)&k0, *(uint32_t*)&k1);
        __half2 w0 = __floats2half2_rn(vx.x, vx.y);
        __half2 w1 = __floats2half2_rn(vx.z, vx.w);
        ((uint2*)&g_Vh[b][t][0])[lane] = make_uint2(*(uint32_t*)&w0, *(uint32_t*)&w1);
    }
}

__global__ void k_buckets(const float* __restrict__ qk, const float* __restrict__ rot) {
    __shared__ float rs[32 * 32];
    __shared__ float qt_[256 * 33];
    int b = blockIdx.z, h = blockIdx.y, tid = threadIdx.x;
    int s0 = blockIdx.x * 256;
    ull acc2[16];
#pragma unroll
    for (int n = 0; n < 16; n++) acc2[n] = 0ull;
    for (int d0 = 0; d0 < 128; d0 += 32) {
        for (int i = tid; i < 32 * 32; i += 256) {
            int dd = i >> 5, nn = i & 31;
            rs[i] = rot[((size_t)(d0 + dd) * NH + h) * 32 + nn];
        }
        for (int i = tid; i < 256 * 32; i += 256) {
            int r = i >> 5, c = i & 31;
            qt_[r * 33 + c] = qk[((size_t)b * SL + s0 + r) * D + d0 + c];
        }
        __syncthreads();
#pragma unroll 4
        for (int dd = 0; dd < 32; dd++) {
            float qv = qt_[tid * 33 + dd];
            ull qq = pack2(qv, qv);
            const ull* r2 = (const ull*)&rs[dd * 32];
#pragma unroll
            for (int n = 0; n < 16; n++) fma2(acc2[n], qq, r2[n]);
        }
        __syncthreads();
    }
    float acc[32];
#pragma unroll
    for (int n = 0; n < 16; n++) { float2 p = unpack2(acc2[n]); acc[2*n] = p.x; acc[2*n+1] = p.y; }
    float best = acc[0]; int idx = 0;
#pragma unroll
    for (int n = 1; n < 32; n++) if (acc[n] > best) { best = acc[n]; idx = n; }
#pragma unroll
    for (int n = 0; n < 32; n++) if (-acc[n] > best) { best = -acc[n]; idx = 32 + n; }
    int bucket = idx + h * NB;
    g_buckets[b][h][s0 + tid] = bucket;
    atomicAdd(&g_hist[b][bucket], 1);
}

__global__ void k_prefix() {
    __shared__ int sh[NC];
    int b = blockIdx.x, tid = threadIdx.x;
    int v = g_hist[b][tid];
    sh[tid] = v;
    __syncthreads();
#pragma unroll
    for (int off = 1; off < NC; off <<= 1) {
        int x = (tid >= off) ? sh[tid - off] : 0;
        __syncthreads();
        sh[tid] += x;
        __syncthreads();
    }
    g_boff[b][tid] = sh[tid] - v;
}

__global__ void k_scatter() {
    int bk = blockIdx.x, b = blockIdx.y;
    int h = bk >> 6;
    int warp = threadIdx.x >> 5, lane = threadIdx.x & 31;
    const int* bb = &g_buckets[b][h][0];
    int t0 = warp * (SL / 4);
    __shared__ int wc[4];
    int cnt = 0;
    for (int base = 0; base < SL / 4; base += 32) {
        bool m = (bb[t0 + base + lane] == bk);
        cnt += __popc(__ballot_sync(0xffffffffu, m));
    }
    if (lane == 0) wc[warp] = cnt;
    __syncthreads();
    int pos = g_boff[b][bk];
#pragma unroll
    for (int w = 0; w < 4; w++) if (w < warp) pos += wc[w];
    for (int base = 0; base < SL / 4; base += 32) {
        int t = t0 + base + lane;
        bool m = (bb[t] == bk);
        unsigned bal = __ballot_sync(0xffffffffu, m);
        if (m) {
            int r = __popc(bal & ((1u << lane) - 1));
            int j = h * SL + t;
            g_sticker[b][pos + r] = j;
            g_undo[b][j] = pos + r;
        }
        pos += __popc(bal);
    }
}

// loc codes, token-order transposed layout.
__global__ void k_loc() {
    int idx = blockIdx.x * 128 + threadIdx.x;
    int b = idx >> 12, t = idx & (SL - 1);
    int val[16];
#pragma unroll
    for (int h = 0; h < NH; h++) {
        int bucket = g_buckets[b][h][t];
        int chunk = g_undo[b][h * SL + t] >> 6;
        val[2 * h]     = bucket * NC + chunk;
        val[2 * h + 1] = bucket * NC + ((chunk + 1) & (NC - 1));
    }
    int4* dst = (int4*)&g_locT[b][t][0];
#pragma unroll
    for (int j = 0; j < 4; j++)
        dst[j] = make_int4(val[4 * j], val[4 * j + 1], val[4 * j + 2], val[4 * j + 3]);
}

// Tensor-core attention. grid (NC, B), block 512 (16 warps), 3 blocks/SM.
// All row gathers hit pre-converted fp16 token arrays (256 B rows).
__global__ void __launch_bounds__(512, 3)
k_attn() {
    extern __shared__ char smemc[];
    int n = blockIdx.x, b = blockIdx.y;
    int tid = threadIdx.x, warp = tid >> 5, lane = tid & 31;
    int sg = warp >> 2, zg = warp & 3;
    int gid = lane >> 2, tig = lane & 3;

    int* qt  = (int*)(smemc + IOFF);
    int* qb  = qt + 64;
    int* kt  = qt + 128;
    int* kb  = qt + 256;
    int* ql1 = qt + 384;
    int* kl  = qt + 896;
    float* rmax = (float*)(smemc + RMAXOFF);
    float* rsum = (float*)(smemc + RSUMOFF);

    int prev = (n + NC - 1) & (NC - 1);

    // ---- batched index loads ----
    int tfq[4], tfp[4];
#pragma unroll
    for (int u = 0; u < 4; u++) {
        tfq[u] = g_sticker[b][n * BS + warp + 16 * u];
        tfp[u] = g_sticker[b][prev * BS + warp + 16 * u];
    }

    // ---- current rows: fp16 Q + K straight copies ----
#pragma unroll
    for (int u = 0; u < 4; u++) {
        int s = warp + 16 * u;
        int t = tfq[u] & (SL - 1), h = tfq[u] >> 12;
        ((uint2*)(smemc + QHOFF + s * RSB))[lane] = ((const uint2*)&g_Qh[b][t][0])[lane];
        ((uint2*)(smemc + KHOFF + s * RSB))[lane] = ((const uint2*)&g_Kh[b][t][0])[lane];
        if (lane == 0) { qt[s] = t; kt[s] = t; }
        if (lane < 4) {
            int4 lv = ((const int4*)&g_locT[b][t][0])[lane];
            *(int4*)&kl[s * 16 + 4 * lane] = lv;
            ql1[s * 8 + 2 * lane]     = lv.x;
            ql1[s * 8 + 2 * lane + 1] = lv.z;
            if (lane == (h >> 1)) {
                int bkt = ((h & 1) ? lv.z : lv.x) >> 9;   // loc1 = bucket*512 + chunk
                kb[s] = bkt; qb[s] = bkt;
            }
        }
    }
    // ---- prev rows: K fp16 only (z = 64 + s) ----
#pragma unroll
    for (int u = 0; u < 4; u++) {
        int s = warp + 16 * u;
        int z = 64 + s;
        int t = tfp[u] & (SL - 1), h = tfp[u] >> 12;
        ((uint2*)(smemc + KHOFF + z * RSB))[lane] = ((const uint2*)&g_Kh[b][t][0])[lane];
        if (lane == 0) kt[z] = t;
        if (lane < 4) {
            int4 lv = ((const int4*)&g_locT[b][t][0])[lane];
            *(int4*)&kl[z * 16 + 4 * lane] = lv;
            if (lane == (h >> 1)) kb[z] = ((h & 1) ? lv.z : lv.x) >> 9;
        }
    }
    __syncthreads();

    // ---- QK via mma.sync: warp computes S[16 s, 32 z] over k=128 ----
    float acc[4][4];
#pragma unroll
    for (int nt = 0; nt < 4; nt++)
#pragma unroll
        for (int j = 0; j < 4; j++) acc[nt][j] = 0.f;

    uint32_t aQ = smem_u32(smemc) + QHOFF + (16 * sg + (lane & 15)) * RSB + ((lane >> 4) * 8) * 2;
    uint32_t aK = smem_u32(smemc) + KHOFF + (32 * zg + (lane & 7)) * RSB + (((lane >> 3) & 1) * 8) * 2;
#pragma unroll
    for (int k = 0; k < 8; k++) {
        uint32_t a0, a1, a2, a3;
        LDSM_X4(a0, a1, a2, a3, aQ + k * 32);
#pragma unroll
        for (int nt = 0; nt < 4; nt++) {
            uint32_t b0, b1;
            LDSM_X2(b0, b1, aK + nt * 8 * RSB + k * 32);
            MMA16816(acc[nt], a0, a1, a2, a3, b0, b1);
        }
    }

    // ---- masks + dup correction ----
    int s_a = 16 * sg + gid, s_b = s_a + 8;
    int qt_a = qt[s_a], qb_a = qb[s_a], qt_b = qt[s_b], qb_b = qb[s_b];
    int4 qa1 = *(int4*)&ql1[s_a * 8], qa2 = *(int4*)&ql1[s_a * 8 + 4];
    int4 qb1 = *(int4*)&ql1[s_b * 8], qb2 = *(int4*)&ql1[s_b * 8 + 4];
    const float scale = 0.08838834764831845f;
#pragma unroll
    for (int nt = 0; nt < 4; nt++) {
#pragma unroll
        for (int col = 0; col < 2; col++) {
            int z = 32 * zg + 8 * nt + 2 * tig + col;
            int ktv = kt[z], kbv = kb[z];
            int4 ka = *(int4*)&kl[z * 16 + 0];
            int4 kb4 = *(int4*)&kl[z * 16 + 4];
            int4 kc = *(int4*)&kl[z * 16 + 8];
            int4 kd = *(int4*)&kl[z * 16 + 12];
            float va = acc[nt][col] * scale;
            float vb = acc[nt][col + 2] * scale;
            if (qt_a < ktv)  va = MNEG;
            if (qt_a == ktv) va = -10000.f;
            if (qb_a != kbv) va = MNEG;
            if (qt_b < ktv)  vb = MNEG;
            if (qt_b == ktv) vb = -10000.f;
            if (qb_b != kbv) vb = MNEG;
            int ca = 0, cb = 0;
            ca += (qa1.x == ka.x)  + (qa1.x == ka.y);
            ca += (qa1.y == ka.z)  + (qa1.y == ka.w);
            ca += (qa1.z == kb4.x) + (qa1.z == kb4.y);
            ca += (qa1.w == kb4.z) + (qa1.w == kb4.w);
            ca += (qa2.x == kc.x)  + (qa2.x == kc.y);
            ca += (qa2.y == kc.z)  + (qa2.y == kc.w);
            ca += (qa2.z == kd.x)  + (qa2.z == kd.y);
            ca += (qa2.w == kd.z)  + (qa2.w == kd.w);
            cb += (qb1.x == ka.x)  + (qb1.x == ka.y);
            cb += (qb1.y == ka.z)  + (qb1.y == ka.w);
            cb += (qb1.z == kb4.x) + (qb1.z == kb4.y);
            cb += (qb1.w == kb4.z) + (qb1.w == kb4.w);
            cb += (qb2.x == kc.x)  + (qb2.x == kc.y);
            cb += (qb2.y == kc.z)  + (qb2.y == kc.w);
            cb += (qb2.z == kd.x)  + (qb2.z == kd.y);
            cb += (qb2.w == kd.z)  + (qb2.w == kd.w);
            acc[nt][col]     = va - __logf((float)ca + 1e-9f);
            acc[nt][col + 2] = vb - __logf((float)cb + 1e-9f);
        }
    }

    // ---- single-pass local softmax; store partials ----
    float mxa = MNEG, mxb = MNEG;
#pragma unroll
    for (int nt = 0; nt < 4; nt++) {
        mxa = fmaxf(mxa, fmaxf(acc[nt][0], acc[nt][1]));
        mxb = fmaxf(mxb, fmaxf(acc[nt][2], acc[nt][3]));
    }
#pragma unroll
    for (int o = 1; o <= 2; o <<= 1) {
        mxa = fmaxf(mxa, __shfl_xor_sync(0xffffffffu, mxa, o));
        mxb = fmaxf(mxb, __shfl_xor_sync(0xffffffffu, mxb, o));
    }
    float sa = 0.f, sb = 0.f;
#pragma unroll
    for (int nt = 0; nt < 4; nt++) {
        acc[nt][0] = __expf(acc[nt][0] - mxa);
        acc[nt][1] = __expf(acc[nt][1] - mxa);
        acc[nt][2] = __expf(acc[nt][2] - mxb);
        acc[nt][3] = __expf(acc[nt][3] - mxb);
        sa += acc[nt][0] + acc[nt][1];
        sb += acc[nt][2] + acc[nt][3];
    }
#pragma unroll
    for (int o = 1; o <= 2; o <<= 1) {
        sa += __shfl_xor_sync(0xffffffffu, sa, o);
        sb += __shfl_xor_sync(0xffffffffu, sb, o);
    }
    if (tig == 0) {
        rmax[s_a * 4 + zg] = mxa; rmax[s_b * 4 + zg] = mxb;
        rsum[s_a * 4 + zg] = sa;  rsum[s_b * 4 + zg] = sb;
    }
    __syncthreads();   // QK reads done; K buffer free, partials visible

    // ---- combine softmax; write P over Q buffer ----
    float4 ra = *(float4*)&rmax[s_a * 4];
    float4 rb = *(float4*)&rmax[s_b * 4];
    float ma = fmaxf(fmaxf(ra.x, ra.y), fmaxf(ra.z, ra.w));
    float mb = fmaxf(fmaxf(rb.x, rb.y), fmaxf(rb.z, rb.w));
    float4 sra = *(float4*)&rsum[s_a * 4];
    float4 srb = *(float4*)&rsum[s_b * 4];
    float suma = sra.x * __expf(ra.x - ma) + sra.y * __expf(ra.y - ma)
               + sra.z * __expf(ra.z - ma) + sra.w * __expf(ra.w - ma);
    float sumb = srb.x * __expf(rb.x - mb) + srb.y * __expf(rb.y - mb)
               + srb.z * __expf(rb.z - mb) + srb.w * __expf(rb.w - mb);
    float fa = __expf(mxa - ma) / suma;
    float fb = __expf(mxb - mb) / sumb;
#pragma unroll
    for (int nt = 0; nt < 4; nt++) {
        int z0 = 32 * zg + 8 * nt + 2 * tig;
        __half2 pa = __floats2half2_rn(acc[nt][0] * fa, acc[nt][1] * fa);
        __half2 pb = __floats2half2_rn(acc[nt][2] * fb, acc[nt][3] * fb);
        *(__half2*)(smemc + QHOFF + s_a * RSB + z0 * 2) = pa;
        *(__half2*)(smemc + QHOFF + s_b * RSB + z0 * 2) = pb;
    }
    if (zg == 0 && tig == 0) {
        g_slog[b][n * BS + s_a] = ma + __logf(suma);
        g_slog[b][n * BS + s_b] = mb + __logf(sumb);
    }

    // ---- V load into the freed K buffer via token ids already in smem ----
#pragma unroll
    for (int u = 0; u < 8; u++) {
        int z = warp + 16 * u;
        int t = kt[z];
        ((uint2*)(smemc + KHOFF + z * RSB))[lane] = ((const uint2*)&g_Vh[b][t][0])[lane];
    }
    __syncthreads();   // P and V visible

    // ---- PV via mma.sync: O[16 s, 32 d] = P · V ----
    float o[4][4];
#pragma unroll
    for (int nt = 0; nt < 4; nt++)
#pragma unroll
        for (int j = 0; j < 4; j++) o[nt][j] = 0.f;

    uint32_t aP = smem_u32(smemc) + QHOFF + (16 * sg + (lane & 15)) * RSB + ((lane >> 4) * 8) * 2;
    uint32_t aV = smem_u32(smemc) + KHOFF + (lane & 15) * RSB + (32 * zg) * 2;
#pragma unroll
    for (int k = 0; k < 8; k++) {
        uint32_t a0, a1, a2, a3;
        LDSM_X4(a0, a1, a2, a3, aP + k * 32);
#pragma unroll
        for (int nt = 0; nt < 4; nt++) {
            uint32_t b0, b1;
            LDSM_X2T(b0, b1, aV + k * 16 * RSB + nt * 16);
            MMA16816(o[nt], a0, a1, a2, a3, b0, b1);
        }
    }
#pragma unroll
    for (int nt = 0; nt < 4; nt++) {
        int d0 = 32 * zg + 8 * nt + 2 * tig;
        *(__half2*)&g_so[b][n * BS + s_a][d0] = __floats2half2_rn(o[nt][0], o[nt][1]);
        *(__half2*)&g_so[b][n * BS + s_b][d0] = __floats2half2_rn(o[nt][2], o[nt][3]);
    }
}

__global__ void k_combine(float* __restrict__ out) {
    int t = blockIdx.x, b = blockIdx.y;
    int d = threadIdx.x;
    int p[NH];
    float l[NH];
    float m = MNEG;
#pragma unroll
    for (int h = 0; h < NH; h++) {
        p[h] = g_undo[b][h * SL + t];
        l[h] = g_slog[b][p[h]];
        m = fmaxf(m, l[h]);
    }
    float sum = 0.f;
#pragma unroll
    for (int h = 0; h < NH; h++) { l[h] = __expf(l[h] - m); sum += l[h]; }
    float inv = 1.f / sum;
    float acc = 0.f;
#pragma unroll
    for (int h = 0; h < NH; h++) acc += l[h] * inv * __half2float(g_so[b][p[h]][d]);
    out[((size_t)b * SL + t) * D + d] = acc;
}

extern "C" void kernel_launch(void* const* d_in, const int* in_sizes, int n_in,
                              void* d_out, int out_size) {
    (void)in_sizes; (void)n_in; (void)out_size;
    const float* qk  = (const float*)d_in[0];
    const float* v   = (const float*)d_in[1];
    const float* rot = (const float*)d_in[2];
    float* out = (float*)d_out;

    cudaFuncSetAttribute(k_attn, cudaFuncAttributeMaxDynamicSharedMemorySize, SMEM_ATTN);

    k_zero_hist<<<B, NC>>>();
    k_tok<<<dim3(SL / 64, B), 256>>>(qk, v);
    k_buckets<<<dim3(SL / 256, NH, B), 256>>>(qk, rot);
    k_prefix<<<B, NC>>>();
    k_scatter<<<dim3(NC, B), 128>>>();
    k_loc<<<(B * SL) / 128, 128>>>();
    k_attn<<<dim3(NC, B), 512, SMEM_ATTN>>>();
    k_combine<<<dim3(SL, B), 128>>>(out);
}